// round 6
// baseline (speedup 1.0000x reference)
#include <cuda_runtime.h>
#include <cuda_bf16.h>

// Problem constants (fixed by the reference setup)
#define MAXN 50000
#define MAXE 800000
#define FEAT 128
#define NHEAD 4
#define CDIM 32
#define NGRAPH 64
#define NEG_SLOPE 0.2f

// ---------------- device scratch (no allocations allowed) ----------------
__device__ __align__(256) float g_xp[MAXN * FEAT];        // projected features [N,128]
__device__ __align__(256) float g_asrc[MAXN * NHEAD];     // per-node src logits [N,4]
__device__ __align__(256) float g_adst[MAXN * NHEAD];     // per-node dst logits [N,4]
__device__ __align__(256) int   g_deg[MAXN];              // in-degree histogram
__device__ __align__(256) int   g_off[MAXN + 1];          // CSR offsets
__device__ __align__(256) int   g_cursor[MAXN];           // CSR fill cursors
__device__ __align__(256) int   g_esrc[MAXE];             // CSR: src node per edge slot
__device__ __align__(256) float g_pooled[NGRAPH * FEAT];  // per-graph feature sums

// ---------------- K0: zero scratch that must start at 0 ----------------
__global__ void zero_kernel(int Nn) {
    int idx = blockIdx.x * blockDim.x + threadIdx.x;
    if (idx < Nn) g_deg[idx] = 0;
    if (idx < NGRAPH * FEAT) g_pooled[idx] = 0.f;
}

// ---------------- K1: xp = x @ W, fused att_src/att_dst dots ----------------
// Block: 256 threads, 32 rows per block.
// Shared: x tile 32x129 (16.5KB, padded) + W K-chunk 32x128 (16KB) = 32.5KB.
__global__ __launch_bounds__(256) void gemm_att_kernel(
    const float* __restrict__ x, const float* __restrict__ W,
    const float* __restrict__ att_s, const float* __restrict__ att_d, int Nn)
{
    __shared__ float sW[32 * FEAT];     // 16KB: one K-chunk of W (rows k..k+31)
    __shared__ float sx[32 * 129];      // 16.5KB padded x tile
    int tid = threadIdx.x;
    int row0 = blockIdx.x * 32;

    // load x tile (32 rows x 32 float4), padded rows
    for (int idx = tid; idx < 32 * 32; idx += 256) {
        int r = idx >> 5, c4 = idx & 31;
        float4 v = make_float4(0.f, 0.f, 0.f, 0.f);
        if (row0 + r < Nn) v = ((const float4*)(x + (size_t)(row0 + r) * FEAT))[c4];
        float* p = &sx[r * 129 + c4 * 4];
        p[0] = v.x; p[1] = v.y; p[2] = v.z; p[3] = v.w;
    }

    int cg = tid & 31;            // column group: output cols cg*4 .. cg*4+3
    int rb = (tid >> 5) * 4;      // rows rb .. rb+3
    float a00=0,a01=0,a02=0,a03=0, a10=0,a11=0,a12=0,a13=0;
    float a20=0,a21=0,a22=0,a23=0, a30=0,a31=0,a32=0,a33=0;

    const float4* W4 = (const float4*)W;

    for (int kc = 0; kc < 4; kc++) {
        __syncthreads();   // protect sW from previous iteration's readers
        for (int idx = tid; idx < 32 * 32; idx += 256) {
            float4 wv = W4[kc * (32 * 32) + idx];
            float* p = &sW[idx * 4];
            p[0] = wv.x; p[1] = wv.y; p[2] = wv.z; p[3] = wv.w;
        }
        __syncthreads();

#pragma unroll 8
        for (int kk = 0; kk < 32; kk++) {
            int k = kc * 32 + kk;
            const float* wp = &sW[kk * FEAT + cg * 4];
            float w0 = wp[0], w1 = wp[1], w2 = wp[2], w3 = wp[3];
            float xa = sx[(rb + 0) * 129 + k];
            float xb = sx[(rb + 1) * 129 + k];
            float xc = sx[(rb + 2) * 129 + k];
            float xd = sx[(rb + 3) * 129 + k];
            a00 += xa * w0; a01 += xa * w1; a02 += xa * w2; a03 += xa * w3;
            a10 += xb * w0; a11 += xb * w1; a12 += xb * w2; a13 += xb * w3;
            a20 += xc * w0; a21 += xc * w1; a22 += xc * w2; a23 += xc * w3;
            a30 += xd * w0; a31 += xd * w1; a32 += xd * w2; a33 += xd * w3;
        }
    }

    // write xp (float4, coalesced)
    if (row0 + rb + 0 < Nn) ((float4*)(g_xp + (size_t)(row0+rb+0)*FEAT))[cg] = make_float4(a00,a01,a02,a03);
    if (row0 + rb + 1 < Nn) ((float4*)(g_xp + (size_t)(row0+rb+1)*FEAT))[cg] = make_float4(a10,a11,a12,a13);
    if (row0 + rb + 2 < Nn) ((float4*)(g_xp + (size_t)(row0+rb+2)*FEAT))[cg] = make_float4(a20,a21,a22,a23);
    if (row0 + rb + 3 < Nn) ((float4*)(g_xp + (size_t)(row0+rb+3)*FEAT))[cg] = make_float4(a30,a31,a32,a33);

    __syncthreads();   // everyone done reading sx in the K loop
    // stash results back into sx for the attention dot products
    {
        float* p0 = &sx[(rb + 0) * 129 + cg * 4];
        p0[0]=a00; p0[1]=a01; p0[2]=a02; p0[3]=a03;
        float* p1 = &sx[(rb + 1) * 129 + cg * 4];
        p1[0]=a10; p1[1]=a11; p1[2]=a12; p1[3]=a13;
        float* p2 = &sx[(rb + 2) * 129 + cg * 4];
        p2[0]=a20; p2[1]=a21; p2[2]=a22; p2[3]=a23;
        float* p3 = &sx[(rb + 3) * 129 + cg * 4];
        p3[0]=a30; p3[1]=a31; p3[2]=a32; p3[3]=a33;
    }
    __syncthreads();

    // attention logits: warp h handles head h across the 32 rows
    if (tid < 128) {
        int h = tid >> 5, rr = tid & 31;
        if (row0 + rr < Nn) {
            float ds = 0.f, dd = 0.f;
#pragma unroll
            for (int c = 0; c < CDIM; c++) {
                float v = sx[rr * 129 + h * CDIM + c];
                ds += v * att_s[h * CDIM + c];
                dd += v * att_d[h * CDIM + c];
            }
            g_asrc[(row0 + rr) * NHEAD + h] = ds;
            g_adst[(row0 + rr) * NHEAD + h] = dd;
        }
    }
}

// ---------------- K2: in-degree histogram (edge_index is int32) ----------------
__global__ void hist_kernel(const int* __restrict__ ei, int E) {
    int idx = blockIdx.x * blockDim.x + threadIdx.x;
    if (idx < E) atomicAdd(&g_deg[ei[E + idx]], 1);
}

// ---------------- K3: single-block prefix sum (offsets) ----------------
__global__ void scan_kernel(int Nn) {
    __shared__ int sh[1024];
    int t = threadIdx.x;
    int CH = (Nn + 1023) >> 10;
    int b = t * CH;
    int e = min(b + CH, Nn);
    int s = 0;
    for (int i = b; i < e; i++) s += g_deg[i];
    sh[t] = s;
    __syncthreads();
    for (int d = 1; d < 1024; d <<= 1) {
        int v = (t >= d) ? sh[t - d] : 0;
        __syncthreads();
        sh[t] += v;
        __syncthreads();
    }
    int run = (t > 0) ? sh[t - 1] : 0;
    if (t == 0) g_off[0] = 0;
    for (int i = b; i < e; i++) { run += g_deg[i]; g_off[i + 1] = run; }
}

// ---------------- K4: cursors = offsets ----------------
__global__ void cursor_kernel(int Nn) {
    int idx = blockIdx.x * blockDim.x + threadIdx.x;
    if (idx < Nn) g_cursor[idx] = g_off[idx];
}

// ---------------- K5: CSR fill (src per slot) ----------------
__global__ void csr_kernel(const int* __restrict__ ei, int E) {
    int idx = blockIdx.x * blockDim.x + threadIdx.x;
    if (idx < E) {
        int d = ei[E + idx];
        int s = ei[idx];
        int pos = atomicAdd(&g_cursor[d], 1);
        g_esrc[pos] = s;
    }
}

// ---------------- K6: fused softmax + aggregate + relu + pool ----------------
// One warp per dst node. Lane owns 4 contiguous output cols [4*lane, 4*lane+4)
// (all within head lane>>3) -> one LDG.128 per lane per gathered row.
__global__ __launch_bounds__(256) void agg_kernel(
    const int* __restrict__ batch, const float* __restrict__ bias, int Nn)
{
    int warp = (blockIdx.x * blockDim.x + threadIdx.x) >> 5;
    int lane = threadIdx.x & 31;
    if (warp >= Nn) return;
    int i = warp;
    int h = lane >> 3;           // head of my 4 columns

    float ad0 = g_adst[i * 4 + 0], ad1 = g_adst[i * 4 + 1];
    float ad2 = g_adst[i * 4 + 2], ad3 = g_adst[i * 4 + 3];
    float as0 = g_asrc[i * 4 + 0], as1 = g_asrc[i * 4 + 1];
    float as2 = g_asrc[i * 4 + 2], as3 = g_asrc[i * 4 + 3];

    // self-loop weights (softmax shift cancels exactly; logits are O(1))
    float e0 = as0 + ad0, e1 = as1 + ad1, e2 = as2 + ad2, e3 = as3 + ad3;
    float ws0 = __expf(fmaxf(e0, NEG_SLOPE * e0));
    float ws1 = __expf(fmaxf(e1, NEG_SLOPE * e1));
    float ws2 = __expf(fmaxf(e2, NEG_SLOPE * e2));
    float ws3 = __expf(fmaxf(e3, NEG_SLOPE * e3));
    float wsh = (h == 0) ? ws0 : (h == 1) ? ws1 : (h == 2) ? ws2 : ws3;

    // self contribution (my 4 columns)
    float4 xi4 = *(const float4*)(g_xp + (size_t)i * FEAT + lane * 4);
    float4 acc;
    acc.x = wsh * xi4.x; acc.y = wsh * xi4.y; acc.z = wsh * xi4.z; acc.w = wsh * xi4.w;

    // per-lane edge-weight partial sums (NO self term here — added once after reduce)
    float s0 = 0.f, s1 = 0.f, s2 = 0.f, s3 = 0.f;

    int beg = g_off[i], end = g_off[i + 1];
    for (int jb = beg; jb < end; jb += 32) {
        int cnt = min(32, end - jb);           // uniform across warp
        int src = 0;
        float w0 = 0.f, w1 = 0.f, w2 = 0.f, w3 = 0.f;
        if (lane < cnt) {
            src = g_esrc[jb + lane];
            float f0 = g_asrc[src * 4 + 0] + ad0;
            float f1 = g_asrc[src * 4 + 1] + ad1;
            float f2 = g_asrc[src * 4 + 2] + ad2;
            float f3 = g_asrc[src * 4 + 3] + ad3;
            w0 = __expf(fmaxf(f0, NEG_SLOPE * f0));
            w1 = __expf(fmaxf(f1, NEG_SLOPE * f1));
            w2 = __expf(fmaxf(f2, NEG_SLOPE * f2));
            w3 = __expf(fmaxf(f3, NEG_SLOPE * f3));
        }
        s0 += w0; s1 += w1; s2 += w2; s3 += w3;

        for (int e = 0; e < cnt; e++) {        // uniform trip count
            int   sj = __shfl_sync(0xffffffffu, src, e);
            float b0 = __shfl_sync(0xffffffffu, w0, e);
            float b1 = __shfl_sync(0xffffffffu, w1, e);
            float b2 = __shfl_sync(0xffffffffu, w2, e);
            float b3 = __shfl_sync(0xffffffffu, w3, e);
            float b  = (h == 0) ? b0 : (h == 1) ? b1 : (h == 2) ? b2 : b3;
            float4 xr = *(const float4*)(g_xp + (size_t)sj * FEAT + lane * 4);
            acc.x += b * xr.x; acc.y += b * xr.y; acc.z += b * xr.z; acc.w += b * xr.w;
        }
    }
    // total edge-weight sums per head (butterfly over lanes)
#pragma unroll
    for (int d = 16; d >= 1; d >>= 1) {
        s0 += __shfl_xor_sync(0xffffffffu, s0, d);
        s1 += __shfl_xor_sync(0xffffffffu, s1, d);
        s2 += __shfl_xor_sync(0xffffffffu, s2, d);
        s3 += __shfl_xor_sync(0xffffffffu, s3, d);
    }
    // add self-loop weight ONCE, pick my head's denominator
    float sh = ((h == 0) ? s0 + ws0 : (h == 1) ? s1 + ws1 : (h == 2) ? s2 + ws2 : s3 + ws3);
    float inv = 1.0f / sh;

    float4 b4 = ((const float4*)bias)[lane];
    float o0 = fmaxf(acc.x * inv + b4.x, 0.f);
    float o1 = fmaxf(acc.y * inv + b4.y, 0.f);
    float o2 = fmaxf(acc.z * inv + b4.z, 0.f);
    float o3 = fmaxf(acc.w * inv + b4.w, 0.f);

    int g = batch[i];
    float* pg = g_pooled + g * FEAT + lane * 4;
    atomicAdd(pg + 0, o0);
    atomicAdd(pg + 1, o1);
    atomicAdd(pg + 2, o2);
    atomicAdd(pg + 3, o3);
}

// ---------------- K7: mean + final linear ----------------
__global__ void final_kernel(const int* __restrict__ batch, int Nn,
                             const float* __restrict__ Wl, const float* __restrict__ bl,
                             float* __restrict__ out)
{
    int t = threadIdx.x;
    if (t >= NGRAPH * 2) return;
    int g = t >> 1, o = t & 1;
    // counts via binary search over sorted batch
    int lo = 0, hi = Nn;
    while (lo < hi) { int m = (lo + hi) >> 1; if (batch[m] < g) lo = m + 1; else hi = m; }
    int c0 = lo;
    lo = 0; hi = Nn;
    while (lo < hi) { int m = (lo + hi) >> 1; if (batch[m] < g + 1) lo = m + 1; else hi = m; }
    int cnt = lo - c0;
    float fc = (float)max(cnt, 1);
    float sum = 0.f;
#pragma unroll 4
    for (int k = 0; k < FEAT; k++) sum += g_pooled[g * FEAT + k] * Wl[k * 2 + o];
    out[g * 2 + o] = sum / fc + bl[o];
}

// ---------------- launch ----------------
extern "C" void kernel_launch(void* const* d_in, const int* in_sizes, int n_in,
                              void* d_out, int out_size)
{
    const float* x     = (const float*)d_in[0];
    const int*   ei    = (const int*)d_in[1];     // int32 on the wire (JAX x64 off)
    const int*   batch = (const int*)d_in[2];     // int32 on the wire
    const float* W     = (const float*)d_in[3];
    const float* att_s = (const float*)d_in[4];
    const float* att_d = (const float*)d_in[5];
    const float* bias  = (const float*)d_in[6];
    const float* Wl    = (const float*)d_in[7];
    const float* bl    = (const float*)d_in[8];
    float* out = (float*)d_out;

    int N = in_sizes[0] / FEAT;
    int E = in_sizes[1] / 2;

    zero_kernel<<<(N + 255) / 256, 256>>>(N);
    gemm_att_kernel<<<(N + 31) / 32, 256>>>(x, W, att_s, att_d, N);
    hist_kernel<<<(E + 255) / 256, 256>>>(ei, E);
    scan_kernel<<<1, 1024>>>(N);
    cursor_kernel<<<(N + 255) / 256, 256>>>(N);
    csr_kernel<<<(E + 255) / 256, 256>>>(ei, E);
    {
        long long threads = (long long)N * 32;
        int blocks = (int)((threads + 255) / 256);
        agg_kernel<<<blocks, 256>>>(batch, bias, N);
    }
    final_kernel<<<1, 128>>>(batch, N, Wl, bl, out);
}

// round 7
// speedup vs baseline: 1.3276x; 1.3276x over previous
#include <cuda_runtime.h>
#include <cuda_bf16.h>

// Problem constants (fixed by the reference setup)
#define MAXN 50000
#define MAXE 800000
#define FEAT 128
#define NHEAD 4
#define CDIM 32
#define NGRAPH 64
#define NEG_SLOPE 0.2f
#define SCAN_BS 256

// ---------------- device scratch (no allocations allowed) ----------------
__device__ __align__(256) float g_xp[MAXN * FEAT];        // projected features [N,128]
__device__ __align__(256) float g_asrc[MAXN * NHEAD];     // per-node src logits [N,4]
__device__ __align__(256) float g_adst[MAXN * NHEAD];     // per-node dst logits [N,4]
__device__ __align__(256) int   g_deg[MAXN];              // in-degree histogram
__device__ __align__(256) int   g_off[MAXN + 1];          // CSR offsets
__device__ __align__(256) int   g_cursor[MAXN];           // CSR fill cursors
__device__ __align__(256) int   g_esrc[MAXE];             // CSR: src node per edge slot
__device__ __align__(256) float g_pooled[NGRAPH * FEAT];  // per-graph feature sums
__device__ __align__(256) int   g_bsum[(MAXN + SCAN_BS - 1) / SCAN_BS];  // block sums
__device__ __align__(256) int   g_bpre[(MAXN + SCAN_BS - 1) / SCAN_BS];  // block prefixes

// ---------------- K0: zero scratch that must start at 0 ----------------
__global__ void zero_kernel(int Nn) {
    int idx = blockIdx.x * blockDim.x + threadIdx.x;
    if (idx < Nn) g_deg[idx] = 0;
    if (idx < NGRAPH * FEAT) g_pooled[idx] = 0.f;
}

// ---------------- K1: xp = x @ W, fused att_src/att_dst dots ----------------
__global__ __launch_bounds__(256) void gemm_att_kernel(
    const float* __restrict__ x, const float* __restrict__ W,
    const float* __restrict__ att_s, const float* __restrict__ att_d, int Nn)
{
    __shared__ float sW[32 * FEAT];     // 16KB: one K-chunk of W (rows k..k+31)
    __shared__ float sx[32 * 129];      // 16.5KB padded x tile
    int tid = threadIdx.x;
    int row0 = blockIdx.x * 32;

    for (int idx = tid; idx < 32 * 32; idx += 256) {
        int r = idx >> 5, c4 = idx & 31;
        float4 v = make_float4(0.f, 0.f, 0.f, 0.f);
        if (row0 + r < Nn) v = ((const float4*)(x + (size_t)(row0 + r) * FEAT))[c4];
        float* p = &sx[r * 129 + c4 * 4];
        p[0] = v.x; p[1] = v.y; p[2] = v.z; p[3] = v.w;
    }

    int cg = tid & 31;            // column group: output cols cg*4 .. cg*4+3
    int rb = (tid >> 5) * 4;      // rows rb .. rb+3
    float a00=0,a01=0,a02=0,a03=0, a10=0,a11=0,a12=0,a13=0;
    float a20=0,a21=0,a22=0,a23=0, a30=0,a31=0,a32=0,a33=0;

    const float4* W4 = (const float4*)W;

    for (int kc = 0; kc < 4; kc++) {
        __syncthreads();
        for (int idx = tid; idx < 32 * 32; idx += 256) {
            float4 wv = W4[kc * (32 * 32) + idx];
            float* p = &sW[idx * 4];
            p[0] = wv.x; p[1] = wv.y; p[2] = wv.z; p[3] = wv.w;
        }
        __syncthreads();

#pragma unroll 8
        for (int kk = 0; kk < 32; kk++) {
            int k = kc * 32 + kk;
            const float* wp = &sW[kk * FEAT + cg * 4];
            float w0 = wp[0], w1 = wp[1], w2 = wp[2], w3 = wp[3];
            float xa = sx[(rb + 0) * 129 + k];
            float xb = sx[(rb + 1) * 129 + k];
            float xc = sx[(rb + 2) * 129 + k];
            float xd = sx[(rb + 3) * 129 + k];
            a00 += xa * w0; a01 += xa * w1; a02 += xa * w2; a03 += xa * w3;
            a10 += xb * w0; a11 += xb * w1; a12 += xb * w2; a13 += xb * w3;
            a20 += xc * w0; a21 += xc * w1; a22 += xc * w2; a23 += xc * w3;
            a30 += xd * w0; a31 += xd * w1; a32 += xd * w2; a33 += xd * w3;
        }
    }

    if (row0 + rb + 0 < Nn) ((float4*)(g_xp + (size_t)(row0+rb+0)*FEAT))[cg] = make_float4(a00,a01,a02,a03);
    if (row0 + rb + 1 < Nn) ((float4*)(g_xp + (size_t)(row0+rb+1)*FEAT))[cg] = make_float4(a10,a11,a12,a13);
    if (row0 + rb + 2 < Nn) ((float4*)(g_xp + (size_t)(row0+rb+2)*FEAT))[cg] = make_float4(a20,a21,a22,a23);
    if (row0 + rb + 3 < Nn) ((float4*)(g_xp + (size_t)(row0+rb+3)*FEAT))[cg] = make_float4(a30,a31,a32,a33);

    __syncthreads();
    {
        float* p0 = &sx[(rb + 0) * 129 + cg * 4];
        p0[0]=a00; p0[1]=a01; p0[2]=a02; p0[3]=a03;
        float* p1 = &sx[(rb + 1) * 129 + cg * 4];
        p1[0]=a10; p1[1]=a11; p1[2]=a12; p1[3]=a13;
        float* p2 = &sx[(rb + 2) * 129 + cg * 4];
        p2[0]=a20; p2[1]=a21; p2[2]=a22; p2[3]=a23;
        float* p3 = &sx[(rb + 3) * 129 + cg * 4];
        p3[0]=a30; p3[1]=a31; p3[2]=a32; p3[3]=a33;
    }
    __syncthreads();

    if (tid < 128) {
        int h = tid >> 5, rr = tid & 31;
        if (row0 + rr < Nn) {
            float ds = 0.f, dd = 0.f;
#pragma unroll
            for (int c = 0; c < CDIM; c++) {
                float v = sx[rr * 129 + h * CDIM + c];
                ds += v * att_s[h * CDIM + c];
                dd += v * att_d[h * CDIM + c];
            }
            g_asrc[(row0 + rr) * NHEAD + h] = ds;
            g_adst[(row0 + rr) * NHEAD + h] = dd;
        }
    }
}

// ---------------- K2: in-degree histogram (edge_index is int32) ----------------
__global__ void hist_kernel(const int* __restrict__ ei, int E) {
    int idx = blockIdx.x * blockDim.x + threadIdx.x;
    if (idx < E) atomicAdd(&g_deg[ei[E + idx]], 1);
}

// ---------------- K3a: per-block degree sums ----------------
__global__ __launch_bounds__(SCAN_BS) void scan_pass1(int Nn) {
    __shared__ int sh[SCAN_BS];
    int i = blockIdx.x * SCAN_BS + threadIdx.x;
    int v = (i < Nn) ? g_deg[i] : 0;
    sh[threadIdx.x] = v;
    __syncthreads();
    for (int d = SCAN_BS / 2; d > 0; d >>= 1) {
        if (threadIdx.x < d) sh[threadIdx.x] += sh[threadIdx.x + d];
        __syncthreads();
    }
    if (threadIdx.x == 0) g_bsum[blockIdx.x] = sh[0];
}

// ---------------- K3b: scan of block sums (nb <= 256) ----------------
__global__ __launch_bounds__(SCAN_BS) void scan_pass2(int nb) {
    __shared__ int sh[SCAN_BS];
    int t = threadIdx.x;
    sh[t] = (t < nb) ? g_bsum[t] : 0;
    __syncthreads();
    for (int d = 1; d < SCAN_BS; d <<= 1) {
        int v = (t >= d) ? sh[t - d] : 0;
        __syncthreads();
        sh[t] += v;
        __syncthreads();
    }
    if (t < nb) g_bpre[t] = (t > 0) ? sh[t - 1] : 0;   // exclusive
}

// ---------------- K3c: per-block exclusive scan + offsets + cursors ----------------
__global__ __launch_bounds__(SCAN_BS) void scan_pass3(int Nn) {
    __shared__ int sh[SCAN_BS];
    int t = threadIdx.x;
    int i = blockIdx.x * SCAN_BS + t;
    int v = (i < Nn) ? g_deg[i] : 0;
    sh[t] = v;
    __syncthreads();
    for (int d = 1; d < SCAN_BS; d <<= 1) {
        int u = (t >= d) ? sh[t - d] : 0;
        __syncthreads();
        sh[t] += u;
        __syncthreads();
    }
    int incl = sh[t];
    int base = g_bpre[blockIdx.x];
    int pre = base + incl - v;          // exclusive prefix
    if (i < Nn) {
        g_off[i] = pre;
        g_cursor[i] = pre;
        if (i == Nn - 1) g_off[Nn] = pre + v;
    }
}

// ---------------- K5: CSR fill (src per slot) ----------------
__global__ void csr_kernel(const int* __restrict__ ei, int E) {
    int idx = blockIdx.x * blockDim.x + threadIdx.x;
    if (idx < E) {
        int d = ei[E + idx];
        int s = ei[idx];
        int pos = atomicAdd(&g_cursor[d], 1);
        g_esrc[pos] = s;
    }
}

// ---------------- K6: fused softmax + aggregate + relu + pool ----------------
// One warp per dst node. Lane owns 4 contiguous cols [4*lane, 4*lane+4) (head
// lane>>3). Shuffle-free: each lane recomputes its head's edge weight (uniform
// broadcast loads + 1 MUFU), so no cross-lane traffic and no final butterfly.
__global__ __launch_bounds__(256) void agg_kernel(
    const int* __restrict__ batch, const float* __restrict__ bias, int Nn)
{
    int warp = (blockIdx.x * blockDim.x + threadIdx.x) >> 5;
    int lane = threadIdx.x & 31;
    if (warp >= Nn) return;
    int i = warp;
    int h = lane >> 3;           // head of my 4 columns

    float adh = g_adst[i * 4 + h];
    float ash = g_asrc[i * 4 + h];

    // self-loop weight for my head (softmax shift cancels exactly)
    float es = ash + adh;
    float wsh = __expf(fmaxf(es, NEG_SLOPE * es));

    float4 xi4 = *(const float4*)(g_xp + (size_t)i * FEAT + lane * 4);
    float4 acc;
    acc.x = wsh * xi4.x; acc.y = wsh * xi4.y; acc.z = wsh * xi4.z; acc.w = wsh * xi4.w;
    float s = wsh;               // every lane of head h accumulates the full head sum

    int beg = g_off[i], end = g_off[i + 1];
#pragma unroll 2
    for (int j = beg; j < end; j++) {
        int sj = g_esrc[j];                          // uniform across warp
        float f = g_asrc[sj * 4 + h] + adh;          // 4 distinct addrs -> 1 sector
        float w = __expf(fmaxf(f, NEG_SLOPE * f));
        s += w;
        float4 xr = *(const float4*)(g_xp + (size_t)sj * FEAT + lane * 4);
        acc.x += w * xr.x; acc.y += w * xr.y; acc.z += w * xr.z; acc.w += w * xr.w;
    }

    float inv = 1.0f / s;
    float4 b4 = ((const float4*)bias)[lane];
    float o0 = fmaxf(acc.x * inv + b4.x, 0.f);
    float o1 = fmaxf(acc.y * inv + b4.y, 0.f);
    float o2 = fmaxf(acc.z * inv + b4.z, 0.f);
    float o3 = fmaxf(acc.w * inv + b4.w, 0.f);

    int g = batch[i];
    float* pg = g_pooled + g * FEAT + lane * 4;
    atomicAdd(pg + 0, o0);
    atomicAdd(pg + 1, o1);
    atomicAdd(pg + 2, o2);
    atomicAdd(pg + 3, o3);
}

// ---------------- K7: mean + final linear ----------------
__global__ void final_kernel(const int* __restrict__ batch, int Nn,
                             const float* __restrict__ Wl, const float* __restrict__ bl,
                             float* __restrict__ out)
{
    int t = threadIdx.x;
    if (t >= NGRAPH * 2) return;
    int g = t >> 1, o = t & 1;
    int lo = 0, hi = Nn;
    while (lo < hi) { int m = (lo + hi) >> 1; if (batch[m] < g) lo = m + 1; else hi = m; }
    int c0 = lo;
    lo = 0; hi = Nn;
    while (lo < hi) { int m = (lo + hi) >> 1; if (batch[m] < g + 1) lo = m + 1; else hi = m; }
    int cnt = lo - c0;
    float fc = (float)max(cnt, 1);
    float sum = 0.f;
#pragma unroll 4
    for (int k = 0; k < FEAT; k++) sum += g_pooled[g * FEAT + k] * Wl[k * 2 + o];
    out[g * 2 + o] = sum / fc + bl[o];
}

// ---------------- launch ----------------
extern "C" void kernel_launch(void* const* d_in, const int* in_sizes, int n_in,
                              void* d_out, int out_size)
{
    const float* x     = (const float*)d_in[0];
    const int*   ei    = (const int*)d_in[1];     // int32 on the wire
    const int*   batch = (const int*)d_in[2];     // int32 on the wire
    const float* W     = (const float*)d_in[3];
    const float* att_s = (const float*)d_in[4];
    const float* att_d = (const float*)d_in[5];
    const float* bias  = (const float*)d_in[6];
    const float* Wl    = (const float*)d_in[7];
    const float* bl    = (const float*)d_in[8];
    float* out = (float*)d_out;

    int N = in_sizes[0] / FEAT;
    int E = in_sizes[1] / 2;
    int nb = (N + SCAN_BS - 1) / SCAN_BS;

    zero_kernel<<<(N + 255) / 256, 256>>>(N);
    gemm_att_kernel<<<(N + 31) / 32, 256>>>(x, W, att_s, att_d, N);
    hist_kernel<<<(E + 255) / 256, 256>>>(ei, E);
    scan_pass1<<<nb, SCAN_BS>>>(N);
    scan_pass2<<<1, SCAN_BS>>>(nb);
    scan_pass3<<<nb, SCAN_BS>>>(N);
    csr_kernel<<<(E + 255) / 256, 256>>>(ei, E);
    {
        long long threads = (long long)N * 32;
        int blocks = (int)((threads + 255) / 256);
        agg_kernel<<<blocks, 256>>>(batch, bias, N);
    }
    final_kernel<<<1, 128>>>(batch, N, Wl, bl, out);
}